// round 13
// baseline (speedup 1.0000x reference)
#include <cuda_runtime.h>
#include <math.h>
#include <stdint.h>
#include <stddef.h>

#define Bdim  64
#define Tdim  512
#define INdim 256
#define Hdim  512
#define G4    2048
#define NBLK  128
#define SHP   516     // h tile row pitch (floats)

typedef unsigned long long ull;

// ---------------- packed f32x2 helpers ----------------
#define PK2(d, lo, hi) \
    asm("mov.b64 %0, {%1, %2};" : "=l"(d) : "f"(lo), "f"(hi))
#define UPK2(lo, hi, v) \
    asm("mov.b64 {%0, %1}, %2;" : "=f"(lo), "=f"(hi) : "l"(v))
#define FMA2(acc, a, b) \
    asm("fma.rn.f32x2 %0, %1, %2, %0;" : "+l"(acc) : "l"(a), "l"(b))

// ---------------- device-global scratch ----------------
__device__ __align__(16) float g_G[(size_t)Bdim * Tdim * G4];
__device__ __align__(16) float g_hs0[(size_t)Bdim * Tdim * Hdim];
__device__ __align__(16) float g_bufA[Bdim * Hdim];
__device__ __align__(16) float g_bufB[Bdim * Hdim];
__device__ __align__(16) float g_h0f[Bdim * Hdim];
__device__ __align__(16) float g_c0f[Bdim * Hdim];
__device__ unsigned g_arrive[NBLK];           // per-CTA arrival flags
__device__ volatile unsigned g_rel[4];        // per-batch-group release words

// ---------------- per-group barrier (32 CTAs per batch group) ----------------
__device__ __forceinline__ void group_barrier(int grp, int ui, unsigned target) {
    __syncthreads();
    const int tid = threadIdx.x;
    if (tid == 0) {
        __threadfence();
        ((volatile unsigned*)g_arrive)[blockIdx.x] = target;
    }
    if (ui == 0) {
        if (tid < 32) {
            while (((volatile unsigned*)g_arrive)[grp * 32 + tid] != target) { }
        }
        __syncthreads();
        if (tid == 0) {
            __threadfence();
            g_rel[grp] = target;
        }
    } else if (tid == 0) {
        while (g_rel[grp] != target) { }
    }
    __syncthreads();
}

// ---------------- GEMM: C[m,n] = sum_k A[m,k]*Bw[n,k] + bias1[n]+bias2[n] ----------------
// BM=128, BN=128, BK=16, 256 threads, 8x8 per thread, f32x2, reg-prefetch pipeline.
// B tile staged PRE-SPLATTED in smem (each value stored as a (v,v) float2 pair),
// so the inner loop's FMA2 b-operands come straight from LDS.128 — no PK2 movs,
// ~16 fewer live regs per thread -> fits the (256,2) 128-reg cap without spills.
// Skips m-blocks whose 128 rows are entirely masked (t0 >= len[b]).
__global__ __launch_bounds__(256, 2) void gemm_nt_bias(
    const float* __restrict__ A,
    const float* __restrict__ Bw,
    const float* __restrict__ bias1,
    const float* __restrict__ bias2,
    const int*   __restrict__ length,
    float* __restrict__ C,
    int K)
{
    const int m0 = blockIdx.y * 128;
    const int n0 = blockIdx.x * 128;
    {   // m-block lies inside one batch element: b = m0/512, t0 = m0%512
        const int b = m0 >> 9, t0 = m0 & 511;
        if (__ldg(&length[b]) <= t0) return;   // fully masked -> gates unused
    }

    __shared__ __align__(16) float As[16 * 132];   // As[k][m]
    __shared__ __align__(16) float Bs[16 * 264];   // Bs[k][2n + {0,1}] duplicated
    const int tid = threadIdx.x;
    const int ty = tid >> 4;   // 8-row group
    const int tx = tid & 15;   // 8-col group

    const int row0 = tid >> 2, row1 = (256 + tid) >> 2, kq = tid & 3;

    ull acc2[4][8];
#pragma unroll
    for (int p = 0; p < 4; ++p)
#pragma unroll
        for (int j = 0; j < 8; ++j) acc2[p][j] = 0ull;

    // prefetch tile 0
    float4 pa0 = __ldg((const float4*)&A[(size_t)(m0 + row0) * K + kq * 4]);
    float4 pa1 = __ldg((const float4*)&A[(size_t)(m0 + row1) * K + kq * 4]);
    float4 pb0 = __ldg((const float4*)&Bw[(size_t)(n0 + row0) * K + kq * 4]);
    float4 pb1 = __ldg((const float4*)&Bw[(size_t)(n0 + row1) * K + kq * 4]);

    for (int k0 = 0; k0 < K; k0 += 16) {
        As[(kq * 4 + 0) * 132 + row0] = pa0.x;
        As[(kq * 4 + 1) * 132 + row0] = pa0.y;
        As[(kq * 4 + 2) * 132 + row0] = pa0.z;
        As[(kq * 4 + 3) * 132 + row0] = pa0.w;
        As[(kq * 4 + 0) * 132 + row1] = pa1.x;
        As[(kq * 4 + 1) * 132 + row1] = pa1.y;
        As[(kq * 4 + 2) * 132 + row1] = pa1.z;
        As[(kq * 4 + 3) * 132 + row1] = pa1.w;
        // B staged duplicated: Bs[k][2n] = Bs[k][2n+1] = Bw[n][k]
        *(float2*)&Bs[(kq * 4 + 0) * 264 + 2 * row0] = make_float2(pb0.x, pb0.x);
        *(float2*)&Bs[(kq * 4 + 1) * 264 + 2 * row0] = make_float2(pb0.y, pb0.y);
        *(float2*)&Bs[(kq * 4 + 2) * 264 + 2 * row0] = make_float2(pb0.z, pb0.z);
        *(float2*)&Bs[(kq * 4 + 3) * 264 + 2 * row0] = make_float2(pb0.w, pb0.w);
        *(float2*)&Bs[(kq * 4 + 0) * 264 + 2 * row1] = make_float2(pb1.x, pb1.x);
        *(float2*)&Bs[(kq * 4 + 1) * 264 + 2 * row1] = make_float2(pb1.y, pb1.y);
        *(float2*)&Bs[(kq * 4 + 2) * 264 + 2 * row1] = make_float2(pb1.z, pb1.z);
        *(float2*)&Bs[(kq * 4 + 3) * 264 + 2 * row1] = make_float2(pb1.w, pb1.w);
        __syncthreads();

        if (k0 + 16 < K) {   // prefetch next tile (overlaps compute)
            int kn = k0 + 16;
            pa0 = __ldg((const float4*)&A[(size_t)(m0 + row0) * K + kn + kq * 4]);
            pa1 = __ldg((const float4*)&A[(size_t)(m0 + row1) * K + kn + kq * 4]);
            pb0 = __ldg((const float4*)&Bw[(size_t)(n0 + row0) * K + kn + kq * 4]);
            pb1 = __ldg((const float4*)&Bw[(size_t)(n0 + row1) * K + kn + kq * 4]);
        }

#pragma unroll
        for (int kk = 0; kk < 16; ++kk) {
            ulonglong2 av0 = *(const ulonglong2*)&As[kk * 132 + ty * 8];      // rows (0,1),(2,3)
            ulonglong2 av1 = *(const ulonglong2*)&As[kk * 132 + ty * 8 + 4];  // rows (4,5),(6,7)
            // duplicated b-operands, ready for FMA2 (cols 8tx..8tx+7)
            ulonglong2 b01 = *(const ulonglong2*)&Bs[kk * 264 + tx * 16];
            ulonglong2 b23 = *(const ulonglong2*)&Bs[kk * 264 + tx * 16 + 4];
            ulonglong2 b45 = *(const ulonglong2*)&Bs[kk * 264 + tx * 16 + 8];
            ulonglong2 b67 = *(const ulonglong2*)&Bs[kk * 264 + tx * 16 + 12];
            ull ap[4] = {av0.x, av0.y, av1.x, av1.y};
            ull bp[8] = {b01.x, b01.y, b23.x, b23.y, b45.x, b45.y, b67.x, b67.y};
#pragma unroll
            for (int p = 0; p < 4; ++p)
#pragma unroll
                for (int j = 0; j < 8; ++j)
                    FMA2(acc2[p][j], ap[p], bp[j]);
        }
        __syncthreads();
    }

    float4 c1a = __ldg((const float4*)&bias1[n0 + tx * 8]);
    float4 c1b = __ldg((const float4*)&bias1[n0 + tx * 8 + 4]);
    float4 c2a = __ldg((const float4*)&bias2[n0 + tx * 8]);
    float4 c2b = __ldg((const float4*)&bias2[n0 + tx * 8 + 4]);
    float bs[8] = {c1a.x + c2a.x, c1a.y + c2a.y, c1a.z + c2a.z, c1a.w + c2a.w,
                   c1b.x + c2b.x, c1b.y + c2b.y, c1b.z + c2b.z, c1b.w + c2b.w};
#pragma unroll
    for (int p = 0; p < 4; ++p) {
        float lo[8], hi[8];
#pragma unroll
        for (int j = 0; j < 8; ++j) UPK2(lo[j], hi[j], acc2[p][j]);
        size_t r0 = (size_t)(m0 + ty * 8 + 2 * p + 0) * G4 + n0 + tx * 8;
        size_t r1 = (size_t)(m0 + ty * 8 + 2 * p + 1) * G4 + n0 + tx * 8;
        *(float4*)&C[r0]     = make_float4(lo[0] + bs[0], lo[1] + bs[1], lo[2] + bs[2], lo[3] + bs[3]);
        *(float4*)&C[r0 + 4] = make_float4(lo[4] + bs[4], lo[5] + bs[5], lo[6] + bs[6], lo[7] + bs[7]);
        *(float4*)&C[r1]     = make_float4(hi[0] + bs[0], hi[1] + bs[1], hi[2] + bs[2], hi[3] + bs[3]);
        *(float4*)&C[r1 + 4] = make_float4(hi[4] + bs[4], hi[5] + bs[5], hi[6] + bs[6], hi[7] + bs[7]);
    }
}

// ---------------- persistent LSTM recurrence ----------------
// 128 CTAs = 4 batch-groups x 32 unit-tiles; 512 threads. Batch groups are
// fully independent -> per-group barrier + early exit at the group's max length.
__global__ __launch_bounds__(512, 1) void lstm_rec(
    const float* __restrict__ Whh,
    const int*   __restrict__ length,
    float*       __restrict__ hs_out,
    int layer)
{
    extern __shared__ float sm[];
    float* sWtp  = sm;                    // [256 kp][128] pair-interleaved W
    float* sH    = sWtp + 256 * 128;      // [16][SHP]
    float* sRed  = sH + 16 * SHP;         // [8][16][64]
    float* sGate = sRed + 8 * 16 * 64;    // [16][68]
    __shared__ int sLen[16];

    const int tid = threadIdx.x;
    const int ui = blockIdx.x & 31, bi = blockIdx.x >> 5;
    const int u0 = ui * 16, b0 = bi * 16;

    const unsigned gen0 = g_rel[bi];      // barrier base (replay-safe)

    // Stage W_hh slice pair-interleaved: sWtp[kp*128 + 2c + p] = W[2kp+p][c].
    for (int i = tid; i < 64 * 128; i += 512) {
        int c = i & 63;
        int kq = i >> 6;
        int grow = (c >> 4) * Hdim + u0 + (c & 15);
        float4 v = __ldg((const float4*)&Whh[(size_t)grow * Hdim + kq * 4]);
        int base = (2 * kq) * 128 + 2 * c;
        *(float2*)&sWtp[base]       = make_float2(v.x, v.y);
        *(float2*)&sWtp[base + 128] = make_float2(v.z, v.w);
    }
    if (tid < 16) sLen[tid] = __ldg(&length[b0 + tid]);

    // state-cell mapping (tid < 256)
    const int ub = tid >> 4, lu = tid & 15;
    const int gb = b0 + (ub & 15);
    const int gu = u0 + lu;
    int   len = 0;
    float h0f_r = 0.f, c0f_r = 0.f;
    float h_reg = 0.f, c_reg = 0.f;
    if (tid < 256) {
        len = __ldg(&length[gb]);
        if (layer) {
            h0f_r = g_h0f[gb * Hdim + gu];
            c0f_r = g_c0f[gb * Hdim + gu];
        }
        g_bufA[gb * Hdim + gu] = 0.f;
    }
    __syncthreads();
    int maxlen = 1;
#pragma unroll
    for (int i = 0; i < 16; ++i) maxlen = max(maxlen, sLen[i]);

    // dot-phase mapping: tid = ks*64 + bq*16 + cq
    const int ks = tid >> 6;
    const int bq = (tid >> 4) & 3;
    const int cq = tid & 15;
    const int kbeg = ks * 64;
    int hrow[4];
#pragma unroll
    for (int r = 0; r < 4; ++r) hrow[r] = (bq * 4 + r) * SHP;

    const int c0c = (tid & 15) * 4;
    const size_t Goff_c = (size_t)(c0c >> 4) * Hdim + u0 + (c0c & 15);

    group_barrier(bi, ui, gen0 + 1);   // publish h(t=-1)=0 within group

    for (int t = 0; t < maxlen; ++t) {
        const float* hrd = (t & 1) ? g_bufB : g_bufA;
        float*       hwr = (t & 1) ? g_bufA : g_bufB;

        float4 Gv = make_float4(0.f, 0.f, 0.f, 0.f);
        if (tid < 256)
            Gv = __ldg((const float4*)&g_G[((size_t)gb * Tdim + t) * G4 + Goff_c]);

        for (int i = tid; i < 16 * 128; i += 512) {
            int bb = i >> 7, kq = i & 127;
            float4 v = __ldcg((const float4*)&hrd[(b0 + bb) * Hdim + kq * 4]);
            *(float4*)&sH[bb * SHP + kq * 4] = v;
        }
        __syncthreads();

        ull acc2[4][4];
#pragma unroll
        for (int r = 0; r < 4; ++r)
#pragma unroll
            for (int j = 0; j < 4; ++j) acc2[r][j] = 0ull;

#pragma unroll 4
        for (int k = kbeg; k < kbeg + 64; k += 4) {
            const int kp = k >> 1;
            const float* wp = &sWtp[kp * 128 + cq * 4];
            ulonglong2 wA0 = *(const ulonglong2*)wp;
            ulonglong2 wB0 = *(const ulonglong2*)(wp + 64);
            ulonglong2 wA1 = *(const ulonglong2*)(wp + 128);
            ulonglong2 wB1 = *(const ulonglong2*)(wp + 192);
#pragma unroll
            for (int r = 0; r < 4; ++r) {
                ulonglong2 hv = *(const ulonglong2*)&sH[hrow[r] + k];
                FMA2(acc2[r][0], hv.x, wA0.x);
                FMA2(acc2[r][1], hv.x, wA0.y);
                FMA2(acc2[r][2], hv.x, wB0.x);
                FMA2(acc2[r][3], hv.x, wB0.y);
                FMA2(acc2[r][0], hv.y, wA1.x);
                FMA2(acc2[r][1], hv.y, wA1.y);
                FMA2(acc2[r][2], hv.y, wB1.x);
                FMA2(acc2[r][3], hv.y, wB1.y);
            }
        }
#pragma unroll
        for (int r = 0; r < 4; ++r) {
            float lo, hi, s0, s1, s2, s3;
            UPK2(lo, hi, acc2[r][0]); s0 = lo + hi;
            UPK2(lo, hi, acc2[r][1]); s1 = lo + hi;
            UPK2(lo, hi, acc2[r][2]); s2 = lo + hi;
            UPK2(lo, hi, acc2[r][3]); s3 = lo + hi;
            int rowoff = ks * 1024 + (bq * 4 + r) * 64;
            *(float2*)&sRed[rowoff + 2 * cq]      = make_float2(s0, s1);
            *(float2*)&sRed[rowoff + 32 + 2 * cq] = make_float2(s2, s3);
        }
        __syncthreads();

        if (tid < 256) {
            float4 s = *(const float4*)&sRed[0 * 1024 + ub * 64 + c0c];
#pragma unroll
            for (int p = 1; p < 8; ++p) {
                float4 v = *(const float4*)&sRed[p * 1024 + ub * 64 + c0c];
                s.x += v.x; s.y += v.y; s.z += v.z; s.w += v.w;
            }
            s.x += Gv.x; s.y += Gv.y; s.z += Gv.z; s.w += Gv.w;
            *(float4*)&sGate[ub * 68 + c0c] = s;
        }
        __syncthreads();

        if (tid < 256) {
            float gi = sGate[ub * 68 + 0  + lu];
            float gf = sGate[ub * 68 + 16 + lu];
            float gg = sGate[ub * 68 + 32 + lu];
            float go = sGate[ub * 68 + 48 + lu];
            float si = 1.f / (1.f + expf(-gi));
            float sf = 1.f / (1.f + expf(-gf));
            float so = 1.f / (1.f + expf(-go));
            float cn = sf * c_reg + si * tanhf(gg);
            float hn = so * tanhf(cn);
            if (t < len) {
                c_reg = cn; h_reg = hn;
            } else if (layer) {
                c_reg = c0f_r; h_reg = h0f_r;   // layer-1 masked: reset to layer-0 final
            }                                    // layer-0 masked: carry
            hwr[gb * Hdim + gu] = h_reg;
            hs_out[((size_t)gb * Tdim + t) * Hdim + gu] = h_reg;
        }

        group_barrier(bi, ui, gen0 + 2 + t);
    }

    // t >= maxlen: all batches in this group masked.
    // Layer 0 (carry): tail value is the frozen h_reg.
    // Layer 1 (reset): tail value is h0f (layer-0 final).
    if (tid < 256) {
        const float h_tail = layer ? h0f_r : h_reg;
        for (int t = maxlen; t < Tdim; ++t)
            hs_out[((size_t)gb * Tdim + t) * Hdim + gu] = h_tail;
        if (layer == 0) {
            g_h0f[gb * Hdim + gu] = h_reg;
            g_c0f[gb * Hdim + gu] = c_reg;
        }
    }
}

// ---------------- tail: out2 = hs1[b=63] ----------------
__global__ void tail_copy(float* __restrict__ out) {
    size_t i = (size_t)blockIdx.x * 256 + threadIdx.x;   // 65536 float4s
    float4 v = *(const float4*)&out[(size_t)63 * Tdim * Hdim + i * 4];
    *(float4*)&out[(size_t)Bdim * Tdim * Hdim + i * 4] = v;
}

// ---------------- launch ----------------
extern "C" void kernel_launch(void* const* d_in, const int* in_sizes, int n_in,
                              void* d_out, int out_size) {
    const float* x    = (const float*)d_in[0];
    const int*   len  = (const int*)  d_in[1];
    const float* Wih0 = (const float*)d_in[2];
    const float* Whh0 = (const float*)d_in[3];
    const float* bih0 = (const float*)d_in[4];
    const float* bhh0 = (const float*)d_in[5];
    const float* Wih1 = (const float*)d_in[6];
    const float* Whh1 = (const float*)d_in[7];
    const float* bih1 = (const float*)d_in[8];
    const float* bhh1 = (const float*)d_in[9];
    float* out = (float*)d_out;

    constexpr size_t REC_SMEM =
        (256 * 128 + 16 * SHP + 8 * 16 * 64 + 16 * 68) * sizeof(float);  // 201216 B
    cudaFuncSetAttribute(lstm_rec, cudaFuncAttributeMaxDynamicSharedMemorySize,
                         (int)REC_SMEM);

    void* pG = nullptr;  cudaGetSymbolAddress(&pG,  g_G);
    void* pH0 = nullptr; cudaGetSymbolAddress(&pH0, g_hs0);

    dim3 gemm_grid(G4 / 128, (Bdim * Tdim) / 128);   // (16, 256)

    // Layer 0
    gemm_nt_bias<<<gemm_grid, 256>>>(x, Wih0, bih0, bhh0, len, (float*)pG, INdim);
    lstm_rec<<<NBLK, 512, REC_SMEM>>>(Whh0, len, (float*)pH0, 0);

    // Layer 1
    gemm_nt_bias<<<gemm_grid, 256>>>((const float*)pH0, Wih1, bih1, bhh1, len,
                                     (float*)pG, Hdim);
    lstm_rec<<<NBLK, 512, REC_SMEM>>>(Whh1, len, out, 1);

    // output tail = hs1[last batch]
    tail_copy<<<256, 256>>>(out);
}

// round 14
// speedup vs baseline: 1.4798x; 1.4798x over previous
#include <cuda_runtime.h>
#include <math.h>
#include <stdint.h>
#include <stddef.h>

#define Bdim  64
#define Tdim  512
#define INdim 256
#define Hdim  512
#define G4    2048
#define NBLK  128
#define SHP   516     // h tile row pitch (floats)

typedef unsigned long long ull;

// ---------------- packed f32x2 helpers ----------------
#define PK2(d, lo, hi) \
    asm("mov.b64 %0, {%1, %2};" : "=l"(d) : "f"(lo), "f"(hi))
#define UPK2(lo, hi, v) \
    asm("mov.b64 {%0, %1}, %2;" : "=f"(lo), "=f"(hi) : "l"(v))
#define FMA2(acc, a, b) \
    asm("fma.rn.f32x2 %0, %1, %2, %0;" : "+l"(acc) : "l"(a), "l"(b))

// ---------------- device-global scratch ----------------
__device__ __align__(16) float g_G[(size_t)Bdim * Tdim * G4];
__device__ __align__(16) float g_hs0[(size_t)Bdim * Tdim * Hdim];
__device__ __align__(16) float g_bufA[Bdim * Hdim];
__device__ __align__(16) float g_bufB[Bdim * Hdim];
__device__ __align__(16) float g_h0f[Bdim * Hdim];
__device__ __align__(16) float g_c0f[Bdim * Hdim];
__device__ unsigned g_arrive[NBLK];           // per-CTA arrival flags
__device__ volatile unsigned g_rel[4];        // per-batch-group release words

// ---------------- per-group barrier (32 CTAs per batch group) ----------------
__device__ __forceinline__ void group_barrier(int grp, int ui, unsigned target) {
    __syncthreads();
    const int tid = threadIdx.x;
    if (tid == 0) {
        __threadfence();
        ((volatile unsigned*)g_arrive)[blockIdx.x] = target;
    }
    if (ui == 0) {
        if (tid < 32) {
            while (((volatile unsigned*)g_arrive)[grp * 32 + tid] != target) { }
        }
        __syncthreads();
        if (tid == 0) {
            __threadfence();
            g_rel[grp] = target;
        }
    } else if (tid == 0) {
        while (g_rel[grp] != target) { }
    }
    __syncthreads();
}

// ---------------- GEMM (R8 config — proven best; do not touch) ----------------
// BM=128, BN=128, BK=16, 256 threads, 8x8 per thread, f32x2, reg-prefetch pipeline.
// Skips m-blocks whose 128 rows are entirely masked (t0 >= len[b]).
__global__ __launch_bounds__(256, 2) void gemm_nt_bias(
    const float* __restrict__ A,
    const float* __restrict__ Bw,
    const float* __restrict__ bias1,
    const float* __restrict__ bias2,
    const int*   __restrict__ length,
    float* __restrict__ C,
    int K)
{
    const int m0 = blockIdx.y * 128;
    const int n0 = blockIdx.x * 128;
    {   // m-block lies inside one batch element: b = m0/512, t0 = m0%512
        const int b = m0 >> 9, t0 = m0 & 511;
        if (__ldg(&length[b]) <= t0) return;   // fully masked -> gates unused
    }

    __shared__ __align__(16) float As[16 * 132];
    __shared__ __align__(16) float Bs[16 * 132];
    const int tid = threadIdx.x;
    const int ty = tid >> 4;   // 8-row group
    const int tx = tid & 15;   // 8-col group

    const int row0 = tid >> 2, row1 = (256 + tid) >> 2, kq = tid & 3;

    ull acc2[4][8];
#pragma unroll
    for (int p = 0; p < 4; ++p)
#pragma unroll
        for (int j = 0; j < 8; ++j) acc2[p][j] = 0ull;

    // prefetch tile 0
    float4 pa0 = __ldg((const float4*)&A[(size_t)(m0 + row0) * K + kq * 4]);
    float4 pa1 = __ldg((const float4*)&A[(size_t)(m0 + row1) * K + kq * 4]);
    float4 pb0 = __ldg((const float4*)&Bw[(size_t)(n0 + row0) * K + kq * 4]);
    float4 pb1 = __ldg((const float4*)&Bw[(size_t)(n0 + row1) * K + kq * 4]);

    for (int k0 = 0; k0 < K; k0 += 16) {
        As[(kq * 4 + 0) * 132 + row0] = pa0.x;
        As[(kq * 4 + 1) * 132 + row0] = pa0.y;
        As[(kq * 4 + 2) * 132 + row0] = pa0.z;
        As[(kq * 4 + 3) * 132 + row0] = pa0.w;
        As[(kq * 4 + 0) * 132 + row1] = pa1.x;
        As[(kq * 4 + 1) * 132 + row1] = pa1.y;
        As[(kq * 4 + 2) * 132 + row1] = pa1.z;
        As[(kq * 4 + 3) * 132 + row1] = pa1.w;
        Bs[(kq * 4 + 0) * 132 + row0] = pb0.x;
        Bs[(kq * 4 + 1) * 132 + row0] = pb0.y;
        Bs[(kq * 4 + 2) * 132 + row0] = pb0.z;
        Bs[(kq * 4 + 3) * 132 + row0] = pb0.w;
        Bs[(kq * 4 + 0) * 132 + row1] = pb1.x;
        Bs[(kq * 4 + 1) * 132 + row1] = pb1.y;
        Bs[(kq * 4 + 2) * 132 + row1] = pb1.z;
        Bs[(kq * 4 + 3) * 132 + row1] = pb1.w;
        __syncthreads();

        if (k0 + 16 < K) {   // prefetch next tile (overlaps compute)
            int kn = k0 + 16;
            pa0 = __ldg((const float4*)&A[(size_t)(m0 + row0) * K + kn + kq * 4]);
            pa1 = __ldg((const float4*)&A[(size_t)(m0 + row1) * K + kn + kq * 4]);
            pb0 = __ldg((const float4*)&Bw[(size_t)(n0 + row0) * K + kn + kq * 4]);
            pb1 = __ldg((const float4*)&Bw[(size_t)(n0 + row1) * K + kn + kq * 4]);
        }

#pragma unroll
        for (int kk = 0; kk < 16; ++kk) {
            ulonglong2 av0 = *(const ulonglong2*)&As[kk * 132 + ty * 8];
            ulonglong2 av1 = *(const ulonglong2*)&As[kk * 132 + ty * 8 + 4];
            float4 bv0 = *(const float4*)&Bs[kk * 132 + tx * 8];
            float4 bv1 = *(const float4*)&Bs[kk * 132 + tx * 8 + 4];
            ull ap[4] = {av0.x, av0.y, av1.x, av1.y};
            ull bp[8];
            PK2(bp[0], bv0.x, bv0.x); PK2(bp[1], bv0.y, bv0.y);
            PK2(bp[2], bv0.z, bv0.z); PK2(bp[3], bv0.w, bv0.w);
            PK2(bp[4], bv1.x, bv1.x); PK2(bp[5], bv1.y, bv1.y);
            PK2(bp[6], bv1.z, bv1.z); PK2(bp[7], bv1.w, bv1.w);
#pragma unroll
            for (int p = 0; p < 4; ++p)
#pragma unroll
                for (int j = 0; j < 8; ++j)
                    FMA2(acc2[p][j], ap[p], bp[j]);
        }
        __syncthreads();
    }

    float4 c1a = __ldg((const float4*)&bias1[n0 + tx * 8]);
    float4 c1b = __ldg((const float4*)&bias1[n0 + tx * 8 + 4]);
    float4 c2a = __ldg((const float4*)&bias2[n0 + tx * 8]);
    float4 c2b = __ldg((const float4*)&bias2[n0 + tx * 8 + 4]);
    float bs[8] = {c1a.x + c2a.x, c1a.y + c2a.y, c1a.z + c2a.z, c1a.w + c2a.w,
                   c1b.x + c2b.x, c1b.y + c2b.y, c1b.z + c2b.z, c1b.w + c2b.w};
#pragma unroll
    for (int p = 0; p < 4; ++p) {
        float lo[8], hi[8];
#pragma unroll
        for (int j = 0; j < 8; ++j) UPK2(lo[j], hi[j], acc2[p][j]);
        size_t r0 = (size_t)(m0 + ty * 8 + 2 * p + 0) * G4 + n0 + tx * 8;
        size_t r1 = (size_t)(m0 + ty * 8 + 2 * p + 1) * G4 + n0 + tx * 8;
        *(float4*)&C[r0]     = make_float4(lo[0] + bs[0], lo[1] + bs[1], lo[2] + bs[2], lo[3] + bs[3]);
        *(float4*)&C[r0 + 4] = make_float4(lo[4] + bs[4], lo[5] + bs[5], lo[6] + bs[6], lo[7] + bs[7]);
        *(float4*)&C[r1]     = make_float4(hi[0] + bs[0], hi[1] + bs[1], hi[2] + bs[2], hi[3] + bs[3]);
        *(float4*)&C[r1 + 4] = make_float4(hi[4] + bs[4], hi[5] + bs[5], hi[6] + bs[6], hi[7] + bs[7]);
    }
}

// ---------------- persistent LSTM recurrence ----------------
// 128 CTAs = 4 batch-groups x 32 unit-tiles; 512 threads.
// NEW: per-CTA the 16 batches are sorted by DESCENDING length into row order
// (perm), dot warps own one 4-row bundle each (bq = tid>>7), and a warp skips
// its dot entirely once t >= bundleMax[bq] (all its rows masked -> gates
// provably discarded by the state update). E[dot work] ~0.62x.
__global__ __launch_bounds__(512, 1) void lstm_rec(
    const float* __restrict__ Whh,
    const int*   __restrict__ length,
    float*       __restrict__ hs_out,
    int layer)
{
    extern __shared__ float sm[];
    float* sWtp  = sm;                    // [256 kp][128] pair-interleaved W
    float* sH    = sWtp + 256 * 128;      // [16][SHP]
    float* sRed  = sH + 16 * SHP;         // [8][16][64]
    float* sGate = sRed + 8 * 16 * 64;    // [16][68]
    __shared__ int sLen[16];
    __shared__ int sPerm[16];             // row -> local batch index (sorted desc)
    __shared__ int sBMax[4];              // bundle max length

    const int tid = threadIdx.x;
    const int ui = blockIdx.x & 31, bi = blockIdx.x >> 5;
    const int u0 = ui * 16, b0 = bi * 16;

    const unsigned gen0 = g_rel[bi];      // barrier base (replay-safe)

    // Stage W_hh slice pair-interleaved: sWtp[kp*128 + 2c + p] = W[2kp+p][c].
    for (int i = tid; i < 64 * 128; i += 512) {
        int c = i & 63;
        int kq = i >> 6;
        int grow = (c >> 4) * Hdim + u0 + (c & 15);
        float4 v = __ldg((const float4*)&Whh[(size_t)grow * Hdim + kq * 4]);
        int base = (2 * kq) * 128 + 2 * c;
        *(float2*)&sWtp[base]       = make_float2(v.x, v.y);
        *(float2*)&sWtp[base + 128] = make_float2(v.z, v.w);
    }
    if (tid < 16) sLen[tid] = __ldg(&length[b0 + tid]);
    __syncthreads();

    // rank-sort the 16 lengths descending (identical result in every CTA)
    if (tid < 16) {
        int L = sLen[tid];
        int rank = 0;
#pragma unroll
        for (int j = 0; j < 16; ++j) {
            int Lj = sLen[j];
            rank += (Lj > L) || (Lj == L && j < tid);
        }
        sPerm[rank] = tid;
    }
    __syncthreads();
    if (tid < 4) sBMax[tid] = sLen[sPerm[tid * 4]];   // first of bundle = its max
    __syncthreads();

    const int maxlen = max(sLen[sPerm[0]], 1);

    // state-cell mapping (tid < 256): row ub <-> batch b0 + sPerm[ub]
    const int ub = tid >> 4, lu = tid & 15;
    int   gb = b0;
    const int gu = u0 + lu;
    int   len = 0;
    float h0f_r = 0.f, c0f_r = 0.f;
    float h_reg = 0.f, c_reg = 0.f;
    if (tid < 256) {
        gb = b0 + sPerm[ub & 15];
        len = sLen[sPerm[ub & 15]];
        if (layer) {
            h0f_r = g_h0f[gb * Hdim + gu];
            c0f_r = g_c0f[gb * Hdim + gu];
        }
        g_bufA[gb * Hdim + gu] = 0.f;
    }

    // dot-phase mapping: bq = tid>>7 (warp-uniform bundle), ks = (tid>>4)&7, cq = tid&15
    const int bq = tid >> 7;
    const int ks = (tid >> 4) & 7;
    const int cq = tid & 15;
    const int kbeg = ks * 64;
    const int bmax = sBMax[bq];           // constant across steps
    int hrow[4];
#pragma unroll
    for (int r = 0; r < 4; ++r) hrow[r] = (bq * 4 + r) * SHP;

    const int c0c = (tid & 15) * 4;
    const size_t Goff_c = (size_t)(c0c >> 4) * Hdim + u0 + (c0c & 15);

    group_barrier(bi, ui, gen0 + 1);   // publish h(t=-1)=0 within group

    for (int t = 0; t < maxlen; ++t) {
        const float* hrd = (t & 1) ? g_bufB : g_bufA;
        float*       hwr = (t & 1) ? g_bufA : g_bufB;

        float4 Gv = make_float4(0.f, 0.f, 0.f, 0.f);
        if (tid < 256)
            Gv = __ldg((const float4*)&g_G[((size_t)gb * Tdim + t) * G4 + Goff_c]);

        // stage h tile, row r holds batch b0+sPerm[r]
        for (int i = tid; i < 16 * 128; i += 512) {
            int bb = i >> 7, kq = i & 127;
            float4 v = __ldcg((const float4*)&hrd[(b0 + sPerm[bb]) * Hdim + kq * 4]);
            *(float4*)&sH[bb * SHP + kq * 4] = v;
        }
        __syncthreads();

        if (t < bmax) {   // whole warp's 4 rows still alive (sorted desc)
            ull acc2[4][4];
#pragma unroll
            for (int r = 0; r < 4; ++r)
#pragma unroll
                for (int j = 0; j < 4; ++j) acc2[r][j] = 0ull;

#pragma unroll 4
            for (int k = kbeg; k < kbeg + 64; k += 4) {
                const int kp = k >> 1;
                const float* wp = &sWtp[kp * 128 + cq * 4];
                ulonglong2 wA0 = *(const ulonglong2*)wp;
                ulonglong2 wB0 = *(const ulonglong2*)(wp + 64);
                ulonglong2 wA1 = *(const ulonglong2*)(wp + 128);
                ulonglong2 wB1 = *(const ulonglong2*)(wp + 192);
#pragma unroll
                for (int r = 0; r < 4; ++r) {
                    ulonglong2 hv = *(const ulonglong2*)&sH[hrow[r] + k];
                    FMA2(acc2[r][0], hv.x, wA0.x);
                    FMA2(acc2[r][1], hv.x, wA0.y);
                    FMA2(acc2[r][2], hv.x, wB0.x);
                    FMA2(acc2[r][3], hv.x, wB0.y);
                    FMA2(acc2[r][0], hv.y, wA1.x);
                    FMA2(acc2[r][1], hv.y, wA1.y);
                    FMA2(acc2[r][2], hv.y, wB1.x);
                    FMA2(acc2[r][3], hv.y, wB1.y);
                }
            }
#pragma unroll
            for (int r = 0; r < 4; ++r) {
                float lo, hi, s0, s1, s2, s3;
                UPK2(lo, hi, acc2[r][0]); s0 = lo + hi;
                UPK2(lo, hi, acc2[r][1]); s1 = lo + hi;
                UPK2(lo, hi, acc2[r][2]); s2 = lo + hi;
                UPK2(lo, hi, acc2[r][3]); s3 = lo + hi;
                int rowoff = ks * 1024 + (bq * 4 + r) * 64;
                *(float2*)&sRed[rowoff + 2 * cq]      = make_float2(s0, s1);
                *(float2*)&sRed[rowoff + 32 + 2 * cq] = make_float2(s2, s3);
            }
        }
        __syncthreads();

        if (tid < 256) {
            // dead rows read stale partials -> garbage gates, but those rows are
            // masked (t >= len) so the state update discards them.
            float4 s = *(const float4*)&sRed[0 * 1024 + ub * 64 + c0c];
#pragma unroll
            for (int p = 1; p < 8; ++p) {
                float4 v = *(const float4*)&sRed[p * 1024 + ub * 64 + c0c];
                s.x += v.x; s.y += v.y; s.z += v.z; s.w += v.w;
            }
            s.x += Gv.x; s.y += Gv.y; s.z += Gv.z; s.w += Gv.w;
            *(float4*)&sGate[ub * 68 + c0c] = s;
        }
        __syncthreads();

        if (tid < 256) {
            float gi = sGate[ub * 68 + 0  + lu];
            float gf = sGate[ub * 68 + 16 + lu];
            float gg = sGate[ub * 68 + 32 + lu];
            float go = sGate[ub * 68 + 48 + lu];
            float si = 1.f / (1.f + expf(-gi));
            float sf = 1.f / (1.f + expf(-gf));
            float so = 1.f / (1.f + expf(-go));
            float cn = sf * c_reg + si * tanhf(gg);
            float hn = so * tanhf(cn);
            if (t < len) {
                c_reg = cn; h_reg = hn;
            } else if (layer) {
                c_reg = c0f_r; h_reg = h0f_r;   // layer-1 masked: reset to layer-0 final
            }                                    // layer-0 masked: carry
            hwr[gb * Hdim + gu] = h_reg;
            hs_out[((size_t)gb * Tdim + t) * Hdim + gu] = h_reg;
        }

        group_barrier(bi, ui, gen0 + 2 + t);
    }

    // t >= maxlen: all batches in this group masked.
    // Layer 0 (carry): tail value is the frozen h_reg.
    // Layer 1 (reset): tail value is h0f (layer-0 final).
    if (tid < 256) {
        const float h_tail = layer ? h0f_r : h_reg;
        for (int t = maxlen; t < Tdim; ++t)
            hs_out[((size_t)gb * Tdim + t) * Hdim + gu] = h_tail;
        if (layer == 0) {
            g_h0f[gb * Hdim + gu] = h_reg;
            g_c0f[gb * Hdim + gu] = c_reg;
        }
    }
}

// ---------------- tail: out2 = hs1[b=63] ----------------
__global__ void tail_copy(float* __restrict__ out) {
    size_t i = (size_t)blockIdx.x * 256 + threadIdx.x;   // 65536 float4s
    float4 v = *(const float4*)&out[(size_t)63 * Tdim * Hdim + i * 4];
    *(float4*)&out[(size_t)Bdim * Tdim * Hdim + i * 4] = v;
}

// ---------------- launch ----------------
extern "C" void kernel_launch(void* const* d_in, const int* in_sizes, int n_in,
                              void* d_out, int out_size) {
    const float* x    = (const float*)d_in[0];
    const int*   len  = (const int*)  d_in[1];
    const float* Wih0 = (const float*)d_in[2];
    const float* Whh0 = (const float*)d_in[3];
    const float* bih0 = (const float*)d_in[4];
    const float* bhh0 = (const float*)d_in[5];
    const float* Wih1 = (const float*)d_in[6];
    const float* Whh1 = (const float*)d_in[7];
    const float* bih1 = (const float*)d_in[8];
    const float* bhh1 = (const float*)d_in[9];
    float* out = (float*)d_out;

    constexpr size_t REC_SMEM =
        (256 * 128 + 16 * SHP + 8 * 16 * 64 + 16 * 68) * sizeof(float);  // 201216 B
    cudaFuncSetAttribute(lstm_rec, cudaFuncAttributeMaxDynamicSharedMemorySize,
                         (int)REC_SMEM);

    void* pG = nullptr;  cudaGetSymbolAddress(&pG,  g_G);
    void* pH0 = nullptr; cudaGetSymbolAddress(&pH0, g_hs0);

    dim3 gemm_grid(G4 / 128, (Bdim * Tdim) / 128);   // (16, 256)

    // Layer 0
    gemm_nt_bias<<<gemm_grid, 256>>>(x, Wih0, bih0, bhh0, len, (float*)pG, INdim);
    lstm_rec<<<NBLK, 512, REC_SMEM>>>(Whh0, len, (float*)pH0, 0);

    // Layer 1
    gemm_nt_bias<<<gemm_grid, 256>>>((const float*)pH0, Wih1, bih1, bhh1, len,
                                     (float*)pG, Hdim);
    lstm_rec<<<NBLK, 512, REC_SMEM>>>(Whh1, len, out, 1);

    // output tail = hs1[last batch]
    tail_copy<<<256, 256>>>(out);
}